// round 13
// baseline (speedup 1.0000x reference)
#include <cuda_runtime.h>

#define HD      768
#define SEQ     256
#define BATCH   4
#define ROWS    1024
#define NP      54
#define THRESH  0.5f
#define ROWOUT  (SEQ * NP)          // 13824
#define CROWS   (ROWS * HD)         // 786432 floats per split buffer
#define NBLK    148                 // persistent tail grid (1 CTA/SM, co-resident)

typedef unsigned long long u64;

// Scratch (device globals — no allocation allowed)
__device__ float g_c[3 * CROWS];          // split-K partials of x @ W1s^T
__device__ float g_habC[ROWS * 2 * HD];   // COMPACT: [slot][ha(768) | hb(768)]
__device__ int   g_cand[ROWS];
__device__ int   g_rows[ROWS];            // slot -> row
__device__ int   g_slot[ROWS];            // row -> slot
__device__ int   g_pairs[BATCH * SEQ * SEQ];
__device__ int   g_cnt;
__device__ int   g_nrows;

// grid-barrier state (monotonic generation: self-resetting, replay-safe)
__device__ int          bar_count = 0;
__device__ volatile int bar_gen   = 0;

__device__ __forceinline__ void grid_barrier()
{
    __syncthreads();
    if (threadIdx.x == 0) {
        int gen = bar_gen;
        __threadfence();
        if (atomicAdd(&bar_count, 1) == NBLK - 1) {
            bar_count = 0;
            __threadfence();
            bar_gen = gen + 1;
        } else {
            while (bar_gen == gen) __nanosleep(64);
            __threadfence();
        }
    }
    __syncthreads();
}

__device__ __forceinline__ void fma2(u64& d, u64 a, u64 b) {
    asm("fma.rn.f32x2 %0, %1, %2, %0;" : "+l"(d) : "l"(a), "l"(b));
}
__device__ __forceinline__ u64 dup2(float a) {
    u64 r; asm("mov.b64 %0, {%1, %1};" : "=l"(r) : "f"(a)); return r;
}
__device__ __forceinline__ void unpack2(float& lo, float& hi, u64 v) {
    asm("mov.b64 {%0, %1}, %2;" : "=f"(lo), "=f"(hi) : "l"(v));
}

// ---------------------------------------------------------------------------
// GEMM: partial c = x[:, ks:ks+256] @ W1s[:, ks:ks+256]^T  -> g_c[split]
// BM=128, BN=64, BK=16, 256 threads, m-pair packed FFMA2, split-K = 3.
// Trickles the 56.6MB output zero-fill through the k-loop.
// ---------------------------------------------------------------------------
#define BM 128
#define BN 64
#define BK 16
#define KSPLIT 256
#define LDA 132
#define LDB 68

__global__ void __launch_bounds__(256, 2) gemm_kernel(
    const float* __restrict__ X,
    const float* __restrict__ W1s,
    float* __restrict__ out)
{
    __shared__ float As[2][BK * LDA];
    __shared__ float Bs[2][BK * LDB];

    const int tid = threadIdx.x;
    const int n0 = blockIdx.x * BN;
    const int m0 = blockIdx.y * BM;
    const int ks = blockIdx.z * KSPLIT;
    const int ty = tid >> 4;
    const int tx = tid & 15;

    const int ctaid = blockIdx.z * 96 + blockIdx.y * 12 + blockIdx.x;  // 0..287
    if (ctaid == 0 && tid == 0) { g_nrows = 0; g_cnt = 0; }
    float4* o4 = (float4*)out + ctaid * 12288 + tid;

    const int am  = tid >> 2;
    const int akq = (tid & 3) * 4;
    const int bn  = tid & 63;
    const int bkq = (tid >> 6) * 4;

    const float* gA0 = X + (m0 + am) * HD + ks + akq;
    const float* gA1 = gA0 + 64 * HD;
    const float* gB  = W1s + (n0 + bn) * HD + ks + bkq;

    u64 acc[4][4];
    #pragma unroll
    for (int j = 0; j < 4; j++)
        #pragma unroll
        for (int ip = 0; ip < 4; ip++) acc[j][ip] = 0ull;

    float4 ra0, ra1, rb;

    ra0 = *(const float4*)gA0;
    ra1 = *(const float4*)gA1;
    rb  = *(const float4*)gB;
    {
        As[0][(akq+0)*LDA + am]      = ra0.x;  As[0][(akq+1)*LDA + am]      = ra0.y;
        As[0][(akq+2)*LDA + am]      = ra0.z;  As[0][(akq+3)*LDA + am]      = ra0.w;
        As[0][(akq+0)*LDA + am + 64] = ra1.x;  As[0][(akq+1)*LDA + am + 64] = ra1.y;
        As[0][(akq+2)*LDA + am + 64] = ra1.z;  As[0][(akq+3)*LDA + am + 64] = ra1.w;
        Bs[0][(bkq+0)*LDB + bn] = rb.x;  Bs[0][(bkq+1)*LDB + bn] = rb.y;
        Bs[0][(bkq+2)*LDB + bn] = rb.z;  Bs[0][(bkq+3)*LDB + bn] = rb.w;
    }
    ra0 = *(const float4*)(gA0 + BK);
    ra1 = *(const float4*)(gA1 + BK);
    rb  = *(const float4*)(gB  + BK);

    const int NITER = KSPLIT / BK;   // 16
    const float4 z4 = make_float4(0.f, 0.f, 0.f, 0.f);

    for (int it = 0; it < NITER; it++) {
        __syncthreads();
        const int cb = it & 1;

        o4[(it * 3 + 0) * 256] = z4;
        o4[(it * 3 + 1) * 256] = z4;
        o4[(it * 3 + 2) * 256] = z4;

        #pragma unroll
        for (int k = 0; k < BK; k++) {
            ulonglong2 a01 = *(const ulonglong2*)&As[cb][k * LDA + ty * 8];
            ulonglong2 a23 = *(const ulonglong2*)&As[cb][k * LDA + ty * 8 + 4];
            float4 bf = *(const float4*)&Bs[cb][k * LDB + tx * 4];
            u64 ap[4] = {a01.x, a01.y, a23.x, a23.y};
            u64 bd[4] = {dup2(bf.x), dup2(bf.y), dup2(bf.z), dup2(bf.w)};
            #pragma unroll
            for (int j = 0; j < 4; j++)
                #pragma unroll
                for (int ip = 0; ip < 4; ip++)
                    fma2(acc[j][ip], ap[ip], bd[j]);
        }

        if (it + 1 < NITER) {
            const int sb = (it + 1) & 1;
            As[sb][(akq+0)*LDA + am]      = ra0.x;  As[sb][(akq+1)*LDA + am]      = ra0.y;
            As[sb][(akq+2)*LDA + am]      = ra0.z;  As[sb][(akq+3)*LDA + am]      = ra0.w;
            As[sb][(akq+0)*LDA + am + 64] = ra1.x;  As[sb][(akq+1)*LDA + am + 64] = ra1.y;
            As[sb][(akq+2)*LDA + am + 64] = ra1.z;  As[sb][(akq+3)*LDA + am + 64] = ra1.w;
            Bs[sb][(bkq+0)*LDB + bn] = rb.x;  Bs[sb][(bkq+1)*LDB + bn] = rb.y;
            Bs[sb][(bkq+2)*LDB + bn] = rb.z;  Bs[sb][(bkq+3)*LDB + bn] = rb.w;
            if (it + 2 < NITER) {
                int ko = (it + 2) * BK;
                ra0 = *(const float4*)(gA0 + ko);
                ra1 = *(const float4*)(gA1 + ko);
                rb  = *(const float4*)(gB  + ko);
            }
        }
    }

    float cv[8][4];
    #pragma unroll
    for (int j = 0; j < 4; j++)
        #pragma unroll
        for (int ip = 0; ip < 4; ip++)
            unpack2(cv[2*ip][j], cv[2*ip+1][j], acc[j][ip]);

    float* cb = g_c + blockIdx.z * CROWS;
    #pragma unroll
    for (int i = 0; i < 8; i++) {
        int m = m0 + ty * 8 + i;
        *(float4*)&cb[m * HD + n0 + tx * 4] =
            make_float4(cv[i][0], cv[i][1], cv[i][2], cv[i][3]);
    }
}

// ---------------------------------------------------------------------------
// TAIL: one persistent kernel (148 blocks, co-resident), 3 phases + 2 barriers
//   P1: cand mask + row/slot lists         (warp per row)
//   P2: pair-list compaction (threads<1024) OVERLAPPED with hab (all warps)
//   P3: pair logits                         (block per pair)
// ---------------------------------------------------------------------------
__global__ void __launch_bounds__(256) tail_kernel(
    const float* __restrict__ X,
    const float* __restrict__ b1s,
    const float* __restrict__ W2s,
    const float* __restrict__ b2s,
    const float* __restrict__ Wp1,
    const float* __restrict__ bp1,
    const float* __restrict__ Wp2,
    const float* __restrict__ bp2,
    float* __restrict__ out)
{
    __shared__ float v[HD];
    const int tid   = threadIdx.x;
    const int gtid  = blockIdx.x * 256 + tid;
    const int gwarp = gtid >> 5;
    const int lane  = tid & 31;
    const int warp  = tid >> 5;

    // ---- Phase 1: candidate mask (warp per row) ----
    if (gwarp < ROWS) {
        const int row = gwarp;
        float s = 0.f;
        #pragma unroll
        for (int t = 0; t < HD / 32; t++) {
            int k = lane + 32 * t;
            float c = g_c[row * HD + k] + g_c[CROWS + row * HD + k]
                    + g_c[2 * CROWS + row * HD + k];
            s += fmaxf(c + b1s[k], 0.f) * W2s[k];
        }
        #pragma unroll
        for (int o = 16; o > 0; o >>= 1)
            s += __shfl_xor_sync(0xffffffffu, s, o);
        if (lane == 0) {
            int c = (s + b2s[0]) > THRESH ? 1 : 0;
            g_cand[row] = c;
            if (c) {
                int r = atomicAdd(&g_nrows, 1);
                g_rows[r] = row;
                g_slot[row] = r;
            }
        }
    }
    __threadfence();
    grid_barrier();

    // ---- Phase 2a: pair-list compaction (global threads < 1024) ----
    if (gtid < ROWS) {
        const int r = gtid;
        if (g_cand[r]) {
            const int b0 = r & ~255;
            const int i  = r & 255;
            int cnt = 0;
            for (int j = 0; j < SEQ; j++)
                if (j != i && g_cand[b0 + j]) cnt++;
            if (cnt) {
                int p = atomicAdd(&g_cnt, cnt);
                for (int j = 0; j < SEQ; j++)
                    if (j != i && g_cand[b0 + j])
                        g_pairs[p++] = r * SEQ + j;     // rowi*256 + j
            }
        }
    }

    // ---- Phase 2b: hab -> compact slot buffer (warp per (slot, col)) ----
    {
        const int nwarps = NBLK * 8;
        const int total  = g_nrows * 1536;
        for (int item = gwarp; item < total; item += nwarps) {
            const int rs  = item / 1536;
            const int c   = item - rs * 1536;
            const int row = g_rows[rs];
            const float4* xr = (const float4*)(X + row * HD);
            const float* wr  = (c < HD) ? (Wp1 + (size_t)c * (2 * HD))
                                        : (Wp1 + (size_t)(c - HD) * (2 * HD) + HD);
            const float4* w4 = (const float4*)wr;
            float s = 0.f;
            #pragma unroll
            for (int t = 0; t < HD / 128; t++) {
                int k = lane + 32 * t;
                float4 xv = __ldg(&xr[k]);
                float4 wv = __ldg(&w4[k]);
                s += xv.x * wv.x + xv.y * wv.y + xv.z * wv.z + xv.w * wv.w;
            }
            #pragma unroll
            for (int o = 16; o > 0; o >>= 1)
                s += __shfl_xor_sync(0xffffffffu, s, o);
            if (lane == 0) g_habC[(size_t)rs * (2 * HD) + c] = s;
        }
    }
    __threadfence();
    grid_barrier();

    // ---- Phase 3: pair logits (block per pair) ----
    {
        const int cnt = g_cnt;
        for (int p = blockIdx.x; p < cnt; p += NBLK) {
            const int code = g_pairs[p];
            const int rowi = code >> 8;
            const int j    = code & 255;
            const int rowj = (rowi & ~255) | j;
            const int si   = g_slot[rowi];
            const int sj   = g_slot[rowj];

            __syncthreads();
            for (int k = tid; k < HD; k += 256)
                v[k] = fmaxf(g_habC[(size_t)si * (2 * HD) + k] +
                             g_habC[(size_t)sj * (2 * HD) + HD + k] + bp1[k], 0.f);
            __syncthreads();

            const int p0 = warp * 7;
            float acc[7];
            #pragma unroll
            for (int q = 0; q < 7; q++) acc[q] = 0.f;

            #pragma unroll
            for (int t = 0; t < HD / 32; t++) {
                int k = lane + 32 * t;
                float vv = v[k];
                #pragma unroll
                for (int q = 0; q < 7; q++) {
                    int pp = p0 + q;
                    if (pp < NP)
                        acc[q] += vv * __ldg(&Wp2[pp * HD + k]);
                }
            }
            #pragma unroll
            for (int q = 0; q < 7; q++) {
                #pragma unroll
                for (int off = 16; off > 0; off >>= 1)
                    acc[q] += __shfl_xor_sync(0xffffffffu, acc[q], off);
            }
            if (lane == 0) {
                float* o = out + (size_t)code * NP;    // code == rowi*SEQ + j
                #pragma unroll
                for (int q = 0; q < 7; q++) {
                    int pp = p0 + q;
                    if (pp < NP) o[pp] = acc[q] + bp2[pp];
                }
            }
        }
    }
}

// ---------------------------------------------------------------------------
extern "C" void kernel_launch(void* const* d_in, const int* in_sizes, int n_in,
                              void* d_out, int out_size)
{
    const float* x   = (const float*)d_in[0];
    const float* W1s = (const float*)d_in[1];
    const float* b1s = (const float*)d_in[2];
    const float* W2s = (const float*)d_in[3];
    const float* b2s = (const float*)d_in[4];
    const float* Wp1 = (const float*)d_in[5];
    const float* bp1 = (const float*)d_in[6];
    const float* Wp2 = (const float*)d_in[7];
    const float* bp2 = (const float*)d_in[8];
    float* out = (float*)d_out;

    // 1) split-K partial GEMM + fused output zero-fill + counter resets
    dim3 g1(HD / BN, ROWS / BM, 3);              // 288 CTAs, single wave
    gemm_kernel<<<g1, 256>>>(x, W1s, out);

    // 2) everything else in ONE persistent kernel (2 grid barriers inside)
    tail_kernel<<<NBLK, 256>>>(x, b1s, W2s, b2s, Wp1, bp1, Wp2, bp2, out);
}

// round 14
// speedup vs baseline: 1.7757x; 1.7757x over previous
#include <cuda_runtime.h>

#define HD      768
#define SEQ     256
#define BATCH   4
#define ROWS    1024
#define NP      54
#define THRESH  0.5f
#define ROWOUT  (SEQ * NP)          // 13824
#define CROWS   (ROWS * HD)         // 786432 floats per split buffer

typedef unsigned long long u64;

// Scratch (device globals — no allocation allowed)
__device__ float g_c[3 * CROWS];          // split-K partials of x @ W1s^T
__device__ float g_habC[ROWS * 2 * HD];   // COMPACT: [slot][ha(768) | hb(768)]
__device__ int   g_cand[ROWS];
__device__ int   g_rows[ROWS];            // slot -> row
__device__ int   g_slot[ROWS];            // row -> slot
__device__ int   g_pairs[BATCH * SEQ * SEQ];
__device__ int   g_cnt;
__device__ int   g_nrows;

__device__ __forceinline__ void fma2(u64& d, u64 a, u64 b) {
    asm("fma.rn.f32x2 %0, %1, %2, %0;" : "+l"(d) : "l"(a), "l"(b));
}
__device__ __forceinline__ u64 dup2(float a) {
    u64 r; asm("mov.b64 %0, {%1, %1};" : "=l"(r) : "f"(a)); return r;
}
__device__ __forceinline__ void unpack2(float& lo, float& hi, u64 v) {
    asm("mov.b64 {%0, %1}, %2;" : "=f"(lo), "=f"(hi) : "l"(v));
}

// ---------------------------------------------------------------------------
// GEMM: partial c = x[:, ks:ks+256] @ W1s[:, ks:ks+256]^T  -> g_c[split]
// BM=128, BN=64, BK=16, 256 threads, m-pair packed FFMA2, split-K = 3.
// Trickles the 56.6MB output zero-fill through the k-loop.
// ---------------------------------------------------------------------------
#define BM 128
#define BN 64
#define BK 16
#define KSPLIT 256
#define LDA 132
#define LDB 68

__global__ void __launch_bounds__(256, 2) gemm_kernel(
    const float* __restrict__ X,
    const float* __restrict__ W1s,
    float* __restrict__ out)
{
    __shared__ float As[2][BK * LDA];
    __shared__ float Bs[2][BK * LDB];

    const int tid = threadIdx.x;
    const int n0 = blockIdx.x * BN;
    const int m0 = blockIdx.y * BM;
    const int ks = blockIdx.z * KSPLIT;
    const int ty = tid >> 4;
    const int tx = tid & 15;

    const int ctaid = blockIdx.z * 96 + blockIdx.y * 12 + blockIdx.x;  // 0..287
    if (ctaid == 0 && tid == 0) { g_nrows = 0; g_cnt = 0; }
    float4* o4 = (float4*)out + ctaid * 12288 + tid;

    const int am  = tid >> 2;
    const int akq = (tid & 3) * 4;
    const int bn  = tid & 63;
    const int bkq = (tid >> 6) * 4;

    const float* gA0 = X + (m0 + am) * HD + ks + akq;
    const float* gA1 = gA0 + 64 * HD;
    const float* gB  = W1s + (n0 + bn) * HD + ks + bkq;

    u64 acc[4][4];
    #pragma unroll
    for (int j = 0; j < 4; j++)
        #pragma unroll
        for (int ip = 0; ip < 4; ip++) acc[j][ip] = 0ull;

    float4 ra0, ra1, rb;

    ra0 = *(const float4*)gA0;
    ra1 = *(const float4*)gA1;
    rb  = *(const float4*)gB;
    {
        As[0][(akq+0)*LDA + am]      = ra0.x;  As[0][(akq+1)*LDA + am]      = ra0.y;
        As[0][(akq+2)*LDA + am]      = ra0.z;  As[0][(akq+3)*LDA + am]      = ra0.w;
        As[0][(akq+0)*LDA + am + 64] = ra1.x;  As[0][(akq+1)*LDA + am + 64] = ra1.y;
        As[0][(akq+2)*LDA + am + 64] = ra1.z;  As[0][(akq+3)*LDA + am + 64] = ra1.w;
        Bs[0][(bkq+0)*LDB + bn] = rb.x;  Bs[0][(bkq+1)*LDB + bn] = rb.y;
        Bs[0][(bkq+2)*LDB + bn] = rb.z;  Bs[0][(bkq+3)*LDB + bn] = rb.w;
    }
    ra0 = *(const float4*)(gA0 + BK);
    ra1 = *(const float4*)(gA1 + BK);
    rb  = *(const float4*)(gB  + BK);

    const int NITER = KSPLIT / BK;   // 16
    const float4 z4 = make_float4(0.f, 0.f, 0.f, 0.f);

    for (int it = 0; it < NITER; it++) {
        __syncthreads();
        const int cb = it & 1;

        o4[(it * 3 + 0) * 256] = z4;
        o4[(it * 3 + 1) * 256] = z4;
        o4[(it * 3 + 2) * 256] = z4;

        #pragma unroll
        for (int k = 0; k < BK; k++) {
            ulonglong2 a01 = *(const ulonglong2*)&As[cb][k * LDA + ty * 8];
            ulonglong2 a23 = *(const ulonglong2*)&As[cb][k * LDA + ty * 8 + 4];
            float4 bf = *(const float4*)&Bs[cb][k * LDB + tx * 4];
            u64 ap[4] = {a01.x, a01.y, a23.x, a23.y};
            u64 bd[4] = {dup2(bf.x), dup2(bf.y), dup2(bf.z), dup2(bf.w)};
            #pragma unroll
            for (int j = 0; j < 4; j++)
                #pragma unroll
                for (int ip = 0; ip < 4; ip++)
                    fma2(acc[j][ip], ap[ip], bd[j]);
        }

        if (it + 1 < NITER) {
            const int sb = (it + 1) & 1;
            As[sb][(akq+0)*LDA + am]      = ra0.x;  As[sb][(akq+1)*LDA + am]      = ra0.y;
            As[sb][(akq+2)*LDA + am]      = ra0.z;  As[sb][(akq+3)*LDA + am]      = ra0.w;
            As[sb][(akq+0)*LDA + am + 64] = ra1.x;  As[sb][(akq+1)*LDA + am + 64] = ra1.y;
            As[sb][(akq+2)*LDA + am + 64] = ra1.z;  As[sb][(akq+3)*LDA + am + 64] = ra1.w;
            Bs[sb][(bkq+0)*LDB + bn] = rb.x;  Bs[sb][(bkq+1)*LDB + bn] = rb.y;
            Bs[sb][(bkq+2)*LDB + bn] = rb.z;  Bs[sb][(bkq+3)*LDB + bn] = rb.w;
            if (it + 2 < NITER) {
                int ko = (it + 2) * BK;
                ra0 = *(const float4*)(gA0 + ko);
                ra1 = *(const float4*)(gA1 + ko);
                rb  = *(const float4*)(gB  + ko);
            }
        }
    }

    float cv[8][4];
    #pragma unroll
    for (int j = 0; j < 4; j++)
        #pragma unroll
        for (int ip = 0; ip < 4; ip++)
            unpack2(cv[2*ip][j], cv[2*ip+1][j], acc[j][ip]);

    float* cb = g_c + blockIdx.z * CROWS;
    #pragma unroll
    for (int i = 0; i < 8; i++) {
        int m = m0 + ty * 8 + i;
        *(float4*)&cb[m * HD + n0 + tx * 4] =
            make_float4(cv[i][0], cv[i][1], cv[i][2], cv[i][3]);
    }
}

// ---------------------------------------------------------------------------
// CAND: warp per row; builds row list + inverse slot map. (128 blocks)
// ---------------------------------------------------------------------------
__global__ void __launch_bounds__(256) cand_kernel(
    const float* __restrict__ b1s,
    const float* __restrict__ W2s,
    const float* __restrict__ b2s)
{
    const int row  = (blockIdx.x * 256 + threadIdx.x) >> 5;
    const int lane = threadIdx.x & 31;
    float s = 0.f;
    #pragma unroll
    for (int t = 0; t < HD / 32; t++) {
        int k = lane + 32 * t;
        float c = g_c[row * HD + k] + g_c[CROWS + row * HD + k]
                + g_c[2 * CROWS + row * HD + k];
        s += fmaxf(c + b1s[k], 0.f) * W2s[k];
    }
    #pragma unroll
    for (int o = 16; o > 0; o >>= 1)
        s += __shfl_xor_sync(0xffffffffu, s, o);
    if (lane == 0) {
        int c = (s + b2s[0]) > THRESH ? 1 : 0;
        g_cand[row] = c;
        if (c) {
            int r = atomicAdd(&g_nrows, 1);
            g_rows[r] = row;
            g_slot[row] = r;
        }
    }
}

// ---------------------------------------------------------------------------
// HABCOMPACT: blocks 0-3 build the pair list (one block per batch);
// blocks 4-1027 compute hab (warp per (slot, col), float4 loads, compact out).
// Both depend only on cand's output; they write disjoint state.
// ---------------------------------------------------------------------------
__global__ void __launch_bounds__(256) habcompact_kernel(
    const float* __restrict__ X,
    const float* __restrict__ Wp1)
{
    if (blockIdx.x < 4) {
        // ---- pair-list compaction for batch b ----
        __shared__ int fc[SEQ];
        const int b = blockIdx.x;
        const int t = threadIdx.x;
        fc[t] = g_cand[b * SEQ + t];
        __syncthreads();
        if (fc[t]) {
            const int i = t;
            int cnt = 0;
            for (int j = 0; j < SEQ; j++)
                if (fc[j] && j != i) cnt++;
            if (cnt) {
                int p = atomicAdd(&g_cnt, cnt);
                for (int j = 0; j < SEQ; j++)
                    if (fc[j] && j != i)
                        g_pairs[p++] = (b * SEQ + i) * SEQ + j;   // rowi*256 + j
            }
        }
        return;
    }

    // ---- hab: warp per (slot, column), 8192 warps total ----
    const int lane   = threadIdx.x & 31;
    const int gwarp  = (blockIdx.x - 4) * 8 + (threadIdx.x >> 5);
    const int nwarps = 1024 * 8;
    const int total  = g_nrows * 1536;

    for (int item = gwarp; item < total; item += nwarps) {
        const int rs  = item / 1536;
        const int c   = item - rs * 1536;
        const int row = g_rows[rs];
        const float4* xr = (const float4*)(X + row * HD);
        const float* wr  = (c < HD) ? (Wp1 + (size_t)c * (2 * HD))
                                    : (Wp1 + (size_t)(c - HD) * (2 * HD) + HD);
        const float4* w4 = (const float4*)wr;
        float s = 0.f;
        #pragma unroll
        for (int t = 0; t < HD / 128; t++) {
            int k = lane + 32 * t;
            float4 xv = __ldg(&xr[k]);
            float4 wv = __ldg(&w4[k]);
            s += xv.x * wv.x + xv.y * wv.y + xv.z * wv.z + xv.w * wv.w;
        }
        #pragma unroll
        for (int o = 16; o > 0; o >>= 1)
            s += __shfl_xor_sync(0xffffffffu, s, o);
        if (lane == 0) g_habC[(size_t)rs * (2 * HD) + c] = s;
    }
}

// ---------------------------------------------------------------------------
// PAIR: list-driven, 2048 blocks -> ~1 pair per block.
// Reads COMPACT habC (L2-hot). 7-accumulator ILP dots per warp.
// ---------------------------------------------------------------------------
__global__ void __launch_bounds__(256) pair_kernel(
    const float* __restrict__ bp1,
    const float* __restrict__ Wp2,
    const float* __restrict__ bp2,
    float* __restrict__ out)
{
    __shared__ float v[HD];
    const int tid  = threadIdx.x;
    const int warp = tid >> 5;
    const int lane = tid & 31;
    const int cnt  = g_cnt;

    for (int p = blockIdx.x; p < cnt; p += gridDim.x) {
        const int code = g_pairs[p];
        const int rowi = code >> 8;
        const int j    = code & 255;
        const int rowj = (rowi & ~255) | j;
        const int si   = g_slot[rowi];
        const int sj   = g_slot[rowj];

        __syncthreads();
        for (int k = tid; k < HD; k += 256)
            v[k] = fmaxf(g_habC[(size_t)si * (2 * HD) + k] +
                         g_habC[(size_t)sj * (2 * HD) + HD + k] + bp1[k], 0.f);
        __syncthreads();

        const int p0 = warp * 7;
        float acc[7];
        #pragma unroll
        for (int q = 0; q < 7; q++) acc[q] = 0.f;

        #pragma unroll
        for (int t = 0; t < HD / 32; t++) {
            int k = lane + 32 * t;
            float vv = v[k];
            #pragma unroll
            for (int q = 0; q < 7; q++) {
                int pp = p0 + q;
                if (pp < NP)
                    acc[q] += vv * __ldg(&Wp2[pp * HD + k]);
            }
        }
        #pragma unroll
        for (int q = 0; q < 7; q++) {
            #pragma unroll
            for (int off = 16; off > 0; off >>= 1)
                acc[q] += __shfl_xor_sync(0xffffffffu, acc[q], off);
        }
        if (lane == 0) {
            float* o = out + (size_t)code * NP;    // code == rowi*SEQ + j
            #pragma unroll
            for (int q = 0; q < 7; q++) {
                int pp = p0 + q;
                if (pp < NP) o[pp] = acc[q] + bp2[pp];
            }
        }
    }
}

// ---------------------------------------------------------------------------
extern "C" void kernel_launch(void* const* d_in, const int* in_sizes, int n_in,
                              void* d_out, int out_size)
{
    const float* x   = (const float*)d_in[0];
    const float* W1s = (const float*)d_in[1];
    const float* b1s = (const float*)d_in[2];
    const float* W2s = (const float*)d_in[3];
    const float* b2s = (const float*)d_in[4];
    const float* Wp1 = (const float*)d_in[5];
    const float* bp1 = (const float*)d_in[6];
    const float* Wp2 = (const float*)d_in[7];
    const float* bp2 = (const float*)d_in[8];
    float* out = (float*)d_out;

    // 1) split-K partial GEMM + fused output zero-fill + counter resets
    dim3 g1(HD / BN, ROWS / BM, 3);              // 288 CTAs, single wave
    gemm_kernel<<<g1, 256>>>(x, W1s, out);

    // 2) candidate mask + row/slot lists (warp per row, wide grid)
    cand_kernel<<<ROWS / 8, 256>>>(b1s, W2s, b2s);

    // 3) pair-list compaction (blocks 0-3) + hab (blocks 4-1027)
    habcompact_kernel<<<1028, 256>>>(x, Wp1);

    // 4) pair logits, list-driven, ~1 pair per block
    pair_kernel<<<2048, 256>>>(bp1, Wp2, bp2, out);
}

// round 15
// speedup vs baseline: 2.2104x; 1.2448x over previous
#include <cuda_runtime.h>

#define HD      768
#define SEQ     256
#define BATCH   4
#define ROWS    1024
#define NP      54
#define THRESH  0.5f
#define ROWOUT  (SEQ * NP)          // 13824
#define CROWS   (ROWS * HD)         // 786432 floats per split buffer

typedef unsigned long long u64;

// Scratch (device globals — no allocation allowed)
__device__ float g_c[3 * CROWS];          // split-K partials of x @ W1s^T
__device__ float g_habC[ROWS * 2 * HD];   // COMPACT: [slot][ha(768) | hb(768)]
__device__ int   g_cand[ROWS];
__device__ int   g_rows[ROWS];            // slot -> row
__device__ int   g_slot[ROWS];            // row -> slot
__device__ int   g_pA[BATCH * SEQ * SEQ];   // (si<<10) | sj
__device__ int   g_pOut[BATCH * SEQ * SEQ]; // rowi*256 + j
__device__ int   g_cnt;
__device__ int   g_nrows;
__device__ float g_dummy;

__device__ __forceinline__ void fma2(u64& d, u64 a, u64 b) {
    asm("fma.rn.f32x2 %0, %1, %2, %0;" : "+l"(d) : "l"(a), "l"(b));
}
__device__ __forceinline__ u64 dup2(float a) {
    u64 r; asm("mov.b64 %0, {%1, %1};" : "=l"(r) : "f"(a)); return r;
}
__device__ __forceinline__ void unpack2(float& lo, float& hi, u64 v) {
    asm("mov.b64 {%0, %1}, %2;" : "=f"(lo), "=f"(hi) : "l"(v));
}

// ---------------------------------------------------------------------------
// GEMM: partial c = x[:, ks:ks+256] @ W1s[:, ks:ks+256]^T  -> g_c[split]
// (unchanged, measured-good) + trickled output zero-fill.
// ---------------------------------------------------------------------------
#define BM 128
#define BN 64
#define BK 16
#define KSPLIT 256
#define LDA 132
#define LDB 68

__global__ void __launch_bounds__(256, 2) gemm_kernel(
    const float* __restrict__ X,
    const float* __restrict__ W1s,
    float* __restrict__ out)
{
    __shared__ float As[2][BK * LDA];
    __shared__ float Bs[2][BK * LDB];

    const int tid = threadIdx.x;
    const int n0 = blockIdx.x * BN;
    const int m0 = blockIdx.y * BM;
    const int ks = blockIdx.z * KSPLIT;
    const int ty = tid >> 4;
    const int tx = tid & 15;

    const int ctaid = blockIdx.z * 96 + blockIdx.y * 12 + blockIdx.x;  // 0..287
    if (ctaid == 0 && tid == 0) { g_nrows = 0; g_cnt = 0; }
    float4* o4 = (float4*)out + ctaid * 12288 + tid;

    const int am  = tid >> 2;
    const int akq = (tid & 3) * 4;
    const int bn  = tid & 63;
    const int bkq = (tid >> 6) * 4;

    const float* gA0 = X + (m0 + am) * HD + ks + akq;
    const float* gA1 = gA0 + 64 * HD;
    const float* gB  = W1s + (n0 + bn) * HD + ks + bkq;

    u64 acc[4][4];
    #pragma unroll
    for (int j = 0; j < 4; j++)
        #pragma unroll
        for (int ip = 0; ip < 4; ip++) acc[j][ip] = 0ull;

    float4 ra0, ra1, rb;

    ra0 = *(const float4*)gA0;
    ra1 = *(const float4*)gA1;
    rb  = *(const float4*)gB;
    {
        As[0][(akq+0)*LDA + am]      = ra0.x;  As[0][(akq+1)*LDA + am]      = ra0.y;
        As[0][(akq+2)*LDA + am]      = ra0.z;  As[0][(akq+3)*LDA + am]      = ra0.w;
        As[0][(akq+0)*LDA + am + 64] = ra1.x;  As[0][(akq+1)*LDA + am + 64] = ra1.y;
        As[0][(akq+2)*LDA + am + 64] = ra1.z;  As[0][(akq+3)*LDA + am + 64] = ra1.w;
        Bs[0][(bkq+0)*LDB + bn] = rb.x;  Bs[0][(bkq+1)*LDB + bn] = rb.y;
        Bs[0][(bkq+2)*LDB + bn] = rb.z;  Bs[0][(bkq+3)*LDB + bn] = rb.w;
    }
    ra0 = *(const float4*)(gA0 + BK);
    ra1 = *(const float4*)(gA1 + BK);
    rb  = *(const float4*)(gB  + BK);

    const int NITER = KSPLIT / BK;   // 16
    const float4 z4 = make_float4(0.f, 0.f, 0.f, 0.f);

    for (int it = 0; it < NITER; it++) {
        __syncthreads();
        const int cb = it & 1;

        o4[(it * 3 + 0) * 256] = z4;
        o4[(it * 3 + 1) * 256] = z4;
        o4[(it * 3 + 2) * 256] = z4;

        #pragma unroll
        for (int k = 0; k < BK; k++) {
            ulonglong2 a01 = *(const ulonglong2*)&As[cb][k * LDA + ty * 8];
            ulonglong2 a23 = *(const ulonglong2*)&As[cb][k * LDA + ty * 8 + 4];
            float4 bf = *(const float4*)&Bs[cb][k * LDB + tx * 4];
            u64 ap[4] = {a01.x, a01.y, a23.x, a23.y};
            u64 bd[4] = {dup2(bf.x), dup2(bf.y), dup2(bf.z), dup2(bf.w)};
            #pragma unroll
            for (int j = 0; j < 4; j++)
                #pragma unroll
                for (int ip = 0; ip < 4; ip++)
                    fma2(acc[j][ip], ap[ip], bd[j]);
        }

        if (it + 1 < NITER) {
            const int sb = (it + 1) & 1;
            As[sb][(akq+0)*LDA + am]      = ra0.x;  As[sb][(akq+1)*LDA + am]      = ra0.y;
            As[sb][(akq+2)*LDA + am]      = ra0.z;  As[sb][(akq+3)*LDA + am]      = ra0.w;
            As[sb][(akq+0)*LDA + am + 64] = ra1.x;  As[sb][(akq+1)*LDA + am + 64] = ra1.y;
            As[sb][(akq+2)*LDA + am + 64] = ra1.z;  As[sb][(akq+3)*LDA + am + 64] = ra1.w;
            Bs[sb][(bkq+0)*LDB + bn] = rb.x;  Bs[sb][(bkq+1)*LDB + bn] = rb.y;
            Bs[sb][(bkq+2)*LDB + bn] = rb.z;  Bs[sb][(bkq+3)*LDB + bn] = rb.w;
            if (it + 2 < NITER) {
                int ko = (it + 2) * BK;
                ra0 = *(const float4*)(gA0 + ko);
                ra1 = *(const float4*)(gA1 + ko);
                rb  = *(const float4*)(gB  + ko);
            }
        }
    }

    float cv[8][4];
    #pragma unroll
    for (int j = 0; j < 4; j++)
        #pragma unroll
        for (int ip = 0; ip < 4; ip++)
            unpack2(cv[2*ip][j], cv[2*ip+1][j], acc[j][ip]);

    float* cb = g_c + blockIdx.z * CROWS;
    #pragma unroll
    for (int i = 0; i < 8; i++) {
        int m = m0 + ty * 8 + i;
        *(float4*)&cb[m * HD + n0 + tx * 4] =
            make_float4(cv[i][0], cv[i][1], cv[i][2], cv[i][3]);
    }
}

// ---------------------------------------------------------------------------
// CAND: warp per row, float4 loads (30 independent LDG.128 per lane).
// ---------------------------------------------------------------------------
__global__ void __launch_bounds__(256) cand_kernel(
    const float* __restrict__ b1s,
    const float* __restrict__ W2s,
    const float* __restrict__ b2s)
{
    const int row  = (blockIdx.x * 256 + threadIdx.x) >> 5;
    const int lane = threadIdx.x & 31;
    const float4* c0 = (const float4*)(g_c + row * HD);
    const float4* c1 = (const float4*)(g_c + CROWS + row * HD);
    const float4* c2 = (const float4*)(g_c + 2 * CROWS + row * HD);
    const float4* b4 = (const float4*)b1s;
    const float4* w4 = (const float4*)W2s;
    float s = 0.f;
    #pragma unroll
    for (int t = 0; t < HD / 128; t++) {       // 6 rounds
        int k = lane + 32 * t;
        float4 a = c0[k], b = c1[k], c = c2[k];
        float4 bb = __ldg(&b4[k]);
        float4 ww = __ldg(&w4[k]);
        s += fmaxf(a.x + b.x + c.x + bb.x, 0.f) * ww.x;
        s += fmaxf(a.y + b.y + c.y + bb.y, 0.f) * ww.y;
        s += fmaxf(a.z + b.z + c.z + bb.z, 0.f) * ww.z;
        s += fmaxf(a.w + b.w + c.w + bb.w, 0.f) * ww.w;
    }
    #pragma unroll
    for (int o = 16; o > 0; o >>= 1)
        s += __shfl_xor_sync(0xffffffffu, s, o);
    if (lane == 0) {
        int c = (s + b2s[0]) > THRESH ? 1 : 0;
        g_cand[row] = c;
        if (c) {
            int r = atomicAdd(&g_nrows, 1);
            g_rows[r] = row;
            g_slot[row] = r;
        }
    }
}

// ---------------------------------------------------------------------------
// HABCOMPACT: blocks 0-3 build the (si,sj)-encoded pair list; blocks 4-1027
// compute hab AND warm Wp2 into L2 (first ~41 blocks, 1 extra load/thread).
// ---------------------------------------------------------------------------
__global__ void __launch_bounds__(256) habcompact_kernel(
    const float* __restrict__ X,
    const float* __restrict__ Wp1,
    const float* __restrict__ Wp2)
{
    if (blockIdx.x < 4) {
        __shared__ int fc[SEQ];
        const int b = blockIdx.x;
        const int t = threadIdx.x;
        fc[t] = g_cand[b * SEQ + t];
        __syncthreads();
        if (fc[t]) {
            const int i = t;
            const int si = g_slot[b * SEQ + i];
            int cnt = 0;
            for (int j = 0; j < SEQ; j++)
                if (fc[j] && j != i) cnt++;
            if (cnt) {
                int p = atomicAdd(&g_cnt, cnt);
                for (int j = 0; j < SEQ; j++)
                    if (fc[j] && j != i) {
                        g_pA[p]   = (si << 10) | g_slot[b * SEQ + j];
                        g_pOut[p] = (b * SEQ + i) * SEQ + j;
                        p++;
                    }
            }
        }
        return;
    }

    // L2-warm Wp2 (NP*HD floats = 10368 float4): first 41 blocks, 1 ld each
    {
        int e = (blockIdx.x - 4) * 256 + threadIdx.x;
        if (e < NP * HD / 4) {
            float4 wv = ((const float4*)Wp2)[e];
            float s = wv.x + wv.y + wv.z + wv.w;
            if (s == 123456.789f) g_dummy = s;   // never true; keeps the load
        }
    }

    // hab: warp per (slot, column), 8192 warps total
    const int lane   = threadIdx.x & 31;
    const int gwarp  = (blockIdx.x - 4) * 8 + (threadIdx.x >> 5);
    const int nwarps = 1024 * 8;
    const int total  = g_nrows * 1536;

    for (int item = gwarp; item < total; item += nwarps) {
        const int rs  = item / 1536;
        const int c   = item - rs * 1536;
        const int row = g_rows[rs];
        const float4* xr = (const float4*)(X + row * HD);
        const float* wr  = (c < HD) ? (Wp1 + (size_t)c * (2 * HD))
                                    : (Wp1 + (size_t)(c - HD) * (2 * HD) + HD);
        const float4* w4 = (const float4*)wr;
        float s = 0.f;
        #pragma unroll
        for (int t = 0; t < HD / 128; t++) {
            int k = lane + 32 * t;
            float4 xv = __ldg(&xr[k]);
            float4 wv = __ldg(&w4[k]);
            s += xv.x * wv.x + xv.y * wv.y + xv.z * wv.z + xv.w * wv.w;
        }
        #pragma unroll
        for (int o = 16; o > 0; o >>= 1)
            s += __shfl_xor_sync(0xffffffffu, s, o);
        if (lane == 0) g_habC[(size_t)rs * (2 * HD) + c] = s;
    }
}

// ---------------------------------------------------------------------------
// PAIR: block per pair (grid-stride). All-float4, max MLP:
//  - prelude: two PARALLEL list loads (si,sj pre-encoded)
//  - v fill: one float4 round (192 items / 256 threads)
//  - dot: 6 rounds x {1 LDS.128 + 7 independent LDG.128} per warp
// warp w handles logits {w, w+8, ..., w+48} (∩ [0,54)).
// ---------------------------------------------------------------------------
__global__ void pair_kernel(
    const float* __restrict__ bp1,
    const float* __restrict__ Wp2,
    const float* __restrict__ bp2,
    float* __restrict__ out)
{
    __shared__ float4 v4[HD / 4];          // 192
    const int tid  = threadIdx.x;
    const int warp = tid >> 5;
    const int lane = tid & 31;
    const int cnt  = g_cnt;
    const float4* w2_4 = (const float4*)Wp2;
    const float4* b1_4 = (const float4*)bp1;

    for (int p = blockIdx.x; p < cnt; p += gridDim.x) {
        const int ab   = g_pA[p];          // parallel loads
        const int code = g_pOut[p];
        const int si   = ab >> 10;
        const int sj   = ab & 1023;

        __syncthreads();
        if (tid < HD / 4) {
            const float4* ha = (const float4*)g_habC + (size_t)si * 384;       // ha block
            const float4* hb = (const float4*)g_habC + (size_t)sj * 384 + 192; // hb block
            float4 a = ha[tid], b = hb[tid], c = __ldg(&b1_4[tid]);
            float4 r;
            r.x = fmaxf(a.x + b.x + c.x, 0.f);
            r.y = fmaxf(a.y + b.y + c.y, 0.f);
            r.z = fmaxf(a.z + b.z + c.z, 0.f);
            r.w = fmaxf(a.w + b.w + c.w, 0.f);
            v4[tid] = r;
        }
        __syncthreads();

        // logits pp = warp + 8q
        float acc[7];
        #pragma unroll
        for (int q = 0; q < 7; q++) acc[q] = 0.f;

        #pragma unroll
        for (int t = 0; t < HD / 128; t++) {          // 6 rounds
            int k = lane + 32 * t;                    // float4 index 0..191
            float4 vv = v4[k];
            #pragma unroll
            for (int q = 0; q < 7; q++) {
                int pp = warp + 8 * q;
                if (pp < NP) {
                    float4 wv = __ldg(&w2_4[pp * (HD / 4) + k]);
                    acc[q] += vv.x * wv.x + vv.y * wv.y + vv.z * wv.z + vv.w * wv.w;
                }
            }
        }
        #pragma unroll
        for (int q = 0; q < 7; q++) {
            #pragma unroll
            for (int off = 16; off > 0; off >>= 1)
                acc[q] += __shfl_xor_sync(0xffffffffu, acc[q], off);
        }
        if (lane == 0) {
            float* o = out + (size_t)code * NP;
            #pragma unroll
            for (int q = 0; q < 7; q++) {
                int pp = warp + 8 * q;
                if (pp < NP) o[pp] = acc[q] + bp2[pp];
            }
        }
    }
}

// ---------------------------------------------------------------------------
extern "C" void kernel_launch(void* const* d_in, const int* in_sizes, int n_in,
                              void* d_out, int out_size)
{
    const float* x   = (const float*)d_in[0];
    const float* W1s = (const float*)d_in[1];
    const float* b1s = (const float*)d_in[2];
    const float* W2s = (const float*)d_in[3];
    const float* b2s = (const float*)d_in[4];
    const float* Wp1 = (const float*)d_in[5];
    const float* bp1 = (const float*)d_in[6];
    const float* Wp2 = (const float*)d_in[7];
    const float* bp2 = (const float*)d_in[8];
    float* out = (float*)d_out;

    // 1) split-K partial GEMM + fused output zero-fill + counter resets
    dim3 g1(HD / BN, ROWS / BM, 3);              // 288 CTAs, single wave
    gemm_kernel<<<g1, 256>>>(x, W1s, out);

    // 2) candidate mask + row/slot lists (float4 loads)
    cand_kernel<<<ROWS / 8, 256>>>(b1s, W2s, b2s);

    // 3) pair-list compaction + hab + Wp2 L2-warm
    habcompact_kernel<<<1028, 256>>>(x, Wp1, Wp2);

    // 4) pair logits, all-float4 high-MLP
    pair_kernel<<<2048, 256>>>(bp1, Wp2, bp2, out);
}